// round 14
// baseline (speedup 1.0000x reference)
#include <cuda_runtime.h>
#include <cuda_bf16.h>
#include <math.h>
#include <stdint.h>

// Problem constants
#define NDIM 8192
#define HDIM 512
#define TAU_INV 2.0f     // 1/0.5
#define EPSV 1e-8f

// MLP tiling (tf32 mma, double-buffered; unchanged from R11)
constexpr int BM = 128, BN = 128, BK = 32;
constexpr int NTHREADS = 256;
constexpr int MLP_SMEM = 4 * 4096 * 4;     // 64 KB

// Sim tiling (bf16 m16n8k16 + cp.async + ldmatrix):
// block 128x256, warp 64x64, BK=32, 4-stage pipeline.
constexpr int SBM = 128, SBN = 256, SBK = 32;
constexpr int STAGES = 4;
constexpr int A_STAGE_B = SBM * SBK * 2;   // 8192 bytes
constexpr int B_STAGE_B = SBN * SBK * 2;   // 16384 bytes
constexpr int STAGE_B = A_STAGE_B + B_STAGE_B;   // 24576
constexpr int SIM_DSMEM = STAGES * STAGE_B + 2 * SBM * 4;   // 99328

// Scratch (static device memory; no allocation allowed)
__device__ float g_h[2ull * NDIM * HDIM];            // hidden activations (32 MB)
__device__ __nv_bfloat16 g_z0b[(size_t)NDIM * HDIM]; // bf16 z0 (8 MB)
__device__ __nv_bfloat16 g_z1b[(size_t)NDIM * HDIM]; // bf16 z1 (8 MB)
__device__ float g_inv0[NDIM];
__device__ float g_inv1[NDIM];
__device__ float g_S[NDIM];
__device__ float g_P[NDIM];

__device__ __forceinline__ uint32_t smem_u32(const void* p) {
    uint32_t a;
    asm("{ .reg .u64 t; cvta.to.shared.u64 t, %1; cvt.u32.u64 %0, t; }"
        : "=r"(a) : "l"(p));
    return a;
}

__device__ __forceinline__ uint32_t f2tf32(float f) {
    uint32_t u;
    asm("cvt.rna.tf32.f32 %0, %1;" : "=r"(u) : "f"(f));
    return u;
}

__device__ __forceinline__ void mma_tf32(float c[4],
                                         const uint32_t a[4],
                                         const uint32_t b[2]) {
    asm volatile(
        "mma.sync.aligned.m16n8k8.row.col.f32.tf32.tf32.f32 "
        "{%0,%1,%2,%3}, {%4,%5,%6,%7}, {%8,%9}, {%0,%1,%2,%3};"
        : "+f"(c[0]), "+f"(c[1]), "+f"(c[2]), "+f"(c[3])
        : "r"(a[0]), "r"(a[1]), "r"(a[2]), "r"(a[3]),
          "r"(b[0]), "r"(b[1]));
}

__device__ __forceinline__ void mma_bf16(float c[4],
                                         const uint32_t a[4],
                                         const uint32_t b[2]) {
    asm volatile(
        "mma.sync.aligned.m16n8k16.row.col.f32.bf16.bf16.f32 "
        "{%0,%1,%2,%3}, {%4,%5,%6,%7}, {%8,%9}, {%0,%1,%2,%3};"
        : "+f"(c[0]), "+f"(c[1]), "+f"(c[2]), "+f"(c[3])
        : "r"(a[0]), "r"(a[1]), "r"(a[2]), "r"(a[3]),
          "r"(b[0]), "r"(b[1]));
}

__device__ __forceinline__ void cp16(uint32_t dst, const void* src) {
    asm volatile("cp.async.cg.shared.global [%0], [%1], 16;"
                 :: "r"(dst), "l"(src) : "memory");
}
#define CP_COMMIT() asm volatile("cp.async.commit_group;" ::: "memory")
#define CP_WAIT(n)  asm volatile("cp.async.wait_group %0;" :: "n"(n) : "memory")

__device__ __forceinline__ void ldsm4(uint32_t& r0, uint32_t& r1,
                                      uint32_t& r2, uint32_t& r3, uint32_t a) {
    asm volatile("ldmatrix.sync.aligned.m8n8.x4.shared.b16 {%0,%1,%2,%3}, [%4];"
                 : "=r"(r0), "=r"(r1), "=r"(r2), "=r"(r3) : "r"(a));
}

// ---------------------------------------------------------------------------
// MLP GEMM (tf32 mma, double-buffered; unchanged from R11)
// ---------------------------------------------------------------------------
__global__ __launch_bounds__(NTHREADS, 1) void gemm_bias_act_mma(
    const float* __restrict__ A0, const float* __restrict__ A1,
    const float* __restrict__ B, const float* __restrict__ bias,
    float* __restrict__ C0, float* __restrict__ C1,
    int K, int Nn, int doElu)
{
    extern __shared__ uint32_t msm[];
    uint32_t* sAb[2] = { msm, msm + 4096 };
    uint32_t* sBb[2] = { msm + 8192, msm + 12288 };

    const float* A = (blockIdx.z == 0) ? A0 : A1;
    float* C = (blockIdx.z == 0) ? C0 : C1;

    const int t = threadIdx.x;
    const int wid = t >> 5, lane = t & 31;
    const int wm = wid >> 2, wn = wid & 3;
    const int rowBase = blockIdx.y * BM;
    const int colBase = blockIdx.x * BN;

    uint32_t offA[4], offB[4];
    const float *gAp[4], *gBp[4];
#pragma unroll
    for (int v = 0; v < 4; v++) {
        int idx = t + v * 256;
        int row = idx >> 3;
        int q   = idx & 7;
        int ks  = q >> 1;
        int e2  = q & 1;
        int mt = row >> 4;
        int rr = row & 15;
        int r  = (rr >> 3) + (e2 << 1);
        offA[v] = (uint32_t)((((((mt << 2) + ks) << 5) + ((rr & 7) << 2)) << 2) + r);
        gAp[v] = A + (size_t)(rowBase + row) * K + (q << 2);
        int nt = row >> 3;
        offB[v] = (uint32_t)((((((nt << 2) + ks) << 5) + ((row & 7) << 2)) << 1) + e2);
        gBp[v] = B + (size_t)(colBase + row) * K + (q << 2);
    }

    float acc[4][4][4];
#pragma unroll
    for (int i = 0; i < 4; i++)
#pragma unroll
        for (int j = 0; j < 4; j++)
#pragma unroll
            for (int r = 0; r < 4; r++) acc[i][j][r] = 0.0f;

    {
#pragma unroll
        for (int v = 0; v < 4; v++) {
            float4 va = *reinterpret_cast<const float4*>(gAp[v]);
            uint32_t* p = &sAb[0][offA[v]];
            p[0]  = f2tf32(va.x); p[4]  = f2tf32(va.y);
            p[8]  = f2tf32(va.z); p[12] = f2tf32(va.w);
            float4 vb = *reinterpret_cast<const float4*>(gBp[v]);
            uint32_t* q2 = &sBb[0][offB[v]];
            q2[0] = f2tf32(vb.x); q2[2] = f2tf32(vb.y);
            q2[4] = f2tf32(vb.z); q2[6] = f2tf32(vb.w);
        }
    }
    __syncthreads();

    const int NITER = K / BK;   // 16
    for (int it = 0; it < NITER; it++) {
        const int cur = it & 1;
        const uint32_t* cA = sAb[cur];
        const uint32_t* cB = sBb[cur];
        const bool pf = (it + 1 < NITER);

        float4 fa[4], fb[4];
        if (pf) {
            const int kn = (it + 1) * BK;
#pragma unroll
            for (int v = 0; v < 4; v++) {
                fa[v] = *reinterpret_cast<const float4*>(gAp[v] + kn);
                fb[v] = *reinterpret_cast<const float4*>(gBp[v] + kn);
            }
        }

#pragma unroll
        for (int ks = 0; ks < 4; ks++) {
            uint32_t af[4][4];
            uint32_t bf[4][2];
#pragma unroll
            for (int am = 0; am < 4; am++) {
                uint4 v = *reinterpret_cast<const uint4*>(
                    &cA[(((((wm << 2) + am) << 2) + ks) << 5 | lane) << 2]);
                af[am][0] = v.x; af[am][1] = v.y; af[am][2] = v.z; af[am][3] = v.w;
            }
#pragma unroll
            for (int bn = 0; bn < 4; bn++) {
                uint2 v = *reinterpret_cast<const uint2*>(
                    &cB[(((((wn << 2) + bn) << 2) + ks) << 5 | lane) << 1]);
                bf[bn][0] = v.x; bf[bn][1] = v.y;
            }
#pragma unroll
            for (int am = 0; am < 4; am++)
#pragma unroll
                for (int bn = 0; bn < 4; bn++)
                    mma_tf32(acc[am][bn], af[am], bf[bn]);
        }

        if (pf) {
            uint32_t* dA = sAb[cur ^ 1];
            uint32_t* dB = sBb[cur ^ 1];
#pragma unroll
            for (int v = 0; v < 4; v++) {
                uint32_t* p = &dA[offA[v]];
                p[0]  = f2tf32(fa[v].x); p[4]  = f2tf32(fa[v].y);
                p[8]  = f2tf32(fa[v].z); p[12] = f2tf32(fa[v].w);
                uint32_t* q2 = &dB[offB[v]];
                q2[0] = f2tf32(fb[v].x); q2[2] = f2tf32(fb[v].y);
                q2[4] = f2tf32(fb[v].z); q2[6] = f2tf32(fb[v].w);
            }
        }
        __syncthreads();
    }

#pragma unroll
    for (int am = 0; am < 4; am++) {
        int row0 = rowBase + wm * 64 + am * 16 + (lane >> 2);
#pragma unroll
        for (int bn = 0; bn < 4; bn++) {
            int col = colBase + wn * 32 + bn * 8 + ((lane & 3) << 1);
            float b0 = bias[col], b1 = bias[col + 1];
            float v0 = acc[am][bn][0] + b0;
            float v1 = acc[am][bn][1] + b1;
            float v2 = acc[am][bn][2] + b0;
            float v3 = acc[am][bn][3] + b1;
            if (doElu) {
                v0 = (v0 > 0.0f) ? v0 : expm1f(v0);
                v1 = (v1 > 0.0f) ? v1 : expm1f(v1);
                v2 = (v2 > 0.0f) ? v2 : expm1f(v2);
                v3 = (v3 > 0.0f) ? v3 : expm1f(v3);
            }
            float2 lo = {v0, v1}, hi = {v2, v3};
            *reinterpret_cast<float2*>(&C[(size_t)row0 * Nn + col]) = lo;
            *reinterpret_cast<float2*>(&C[(size_t)(row0 + 8) * Nn + col]) = hi;
        }
    }
}

// ---------------------------------------------------------------------------
// Row norms (inverse) + zero S/P accumulators + emit bf16 copies of z0/z1.
// ---------------------------------------------------------------------------
__global__ void norm_init_kernel(const float* __restrict__ z0,
                                 const float* __restrict__ z1)
{
    int b = blockIdx.x;
    int row = (b < NDIM) ? b : (b - NDIM);
    const float* z = (b < NDIM) ? z0 : z1;
    __nv_bfloat16* zb = (b < NDIM) ? g_z0b : g_z1b;

    float4 v = *reinterpret_cast<const float4*>(
        &z[(size_t)row * HDIM + threadIdx.x * 4]);

    __nv_bfloat162 p0 = __floats2bfloat162_rn(v.x, v.y);
    __nv_bfloat162 p1 = __floats2bfloat162_rn(v.z, v.w);
    uint2 packed = { *reinterpret_cast<uint32_t*>(&p0),
                     *reinterpret_cast<uint32_t*>(&p1) };
    *reinterpret_cast<uint2*>(&zb[(size_t)row * HDIM + threadIdx.x * 4]) = packed;

    float ss = v.x * v.x + v.y * v.y + v.z * v.z + v.w * v.w;
#pragma unroll
    for (int off = 16; off; off >>= 1)
        ss += __shfl_xor_sync(0xffffffffu, ss, off);

    __shared__ float sred[4];
    if ((threadIdx.x & 31) == 0) sred[threadIdx.x >> 5] = ss;
    __syncthreads();
    if (threadIdx.x == 0) {
        float tot = sred[0] + sred[1] + sred[2] + sred[3];
        float inv = 1.0f / sqrtf(tot);
        if (b < NDIM) {
            g_inv0[row] = inv;
            g_S[row] = 0.0f;
            g_P[row] = 0.0f;
        } else {
            g_inv1[row] = inv;
        }
    }
}

// ---------------------------------------------------------------------------
// Fused similarity: bf16 m16n8k16, cp.async 4-stage pipeline, ldmatrix frags.
// smem per stage: A planes [kc∈0..3][row 0..127]*16B (8KB) then
//                 B planes [kc][n 0..255]*16B (16KB).
// ---------------------------------------------------------------------------
__global__ __launch_bounds__(NTHREADS, 1) void sim_fused_bf16(
    const float* __restrict__ pos)
{
    extern __shared__ uint32_t dynsmem[];
    const uint32_t smemBase = smem_u32(dynsmem);
    float* sS = (float*)((char*)dynsmem + STAGES * STAGE_B);
    float* sP = sS + SBM;

    const int t = threadIdx.x;
    const int wid = t >> 5, lane = t & 31;
    const int wm = wid >> 2, wn = wid & 3;
    const int rowBase = blockIdx.y * SBM;
    const int colBase = blockIdx.x * SBN;

    if (t < SBM) { sS[t] = 0.0f; sP[t] = 0.0f; }

    // Producer chunk descriptors (chunk-invariant).
    const __nv_bfloat16* aSrc[2]; uint32_t aDst[2];
    const __nv_bfloat16* bSrc[4]; uint32_t bDst[4];
#pragma unroll
    for (int v = 0; v < 2; v++) {
        int idx = t + v * 256;
        int row = idx & 127, kc = idx >> 7;
        aDst[v] = (uint32_t)(kc * 2048 + row * 16);
        aSrc[v] = g_z0b + (size_t)(rowBase + row) * HDIM + kc * 8;
    }
#pragma unroll
    for (int v = 0; v < 4; v++) {
        int idx = t + v * 256;
        int n = idx & 255, kc = idx >> 8;
        bDst[v] = (uint32_t)(A_STAGE_B + kc * 4096 + n * 16);
        bSrc[v] = g_z1b + (size_t)(colBase + n) * HDIM + kc * 8;
    }

    // ldmatrix per-lane addresses (stage- and ks-invariant bases).
    const int gq = lane >> 3, rig = lane & 7;
    uint32_t aBase[4], bBase[4];
#pragma unroll
    for (int am = 0; am < 4; am++)
        aBase[am] = (uint32_t)((gq >> 1) * 2048
                    + (wm * 64 + am * 16 + ((gq & 1) << 3) + rig) * 16);
#pragma unroll
    for (int bp = 0; bp < 4; bp++)
        bBase[bp] = (uint32_t)(A_STAGE_B + (gq & 1) * 4096
                    + (wn * 64 + bp * 16 + ((gq >> 1) << 3) + rig) * 16);

    float acc[4][8][4];
#pragma unroll
    for (int i = 0; i < 4; i++)
#pragma unroll
        for (int j = 0; j < 8; j++)
#pragma unroll
            for (int r = 0; r < 4; r++) acc[i][j][r] = 0.0f;

    // Prologue: issue stages 0..2
#pragma unroll
    for (int s = 0; s < STAGES - 1; s++) {
        uint32_t sb = smemBase + s * STAGE_B;
        int ko = s * SBK;
#pragma unroll
        for (int v = 0; v < 2; v++) cp16(sb + aDst[v], aSrc[v] + ko);
#pragma unroll
        for (int v = 0; v < 4; v++) cp16(sb + bDst[v], bSrc[v] + ko);
        CP_COMMIT();
    }

    const int NITER = HDIM / SBK;   // 16
    for (int it = 0; it < NITER; it++) {
        // Wait for stage `it` to land (tail drains with smaller counts)
        if (it < NITER - 2)      CP_WAIT(2);
        else if (it == NITER - 2) CP_WAIT(1);
        else                      CP_WAIT(0);
        __syncthreads();   // all warps done reading buf (it-1)&3 before refill

        if (it + STAGES - 1 < NITER) {
            int s = it + STAGES - 1;
            uint32_t sb = smemBase + (s & 3) * STAGE_B;
            int ko = s * SBK;
#pragma unroll
            for (int v = 0; v < 2; v++) cp16(sb + aDst[v], aSrc[v] + ko);
#pragma unroll
            for (int v = 0; v < 4; v++) cp16(sb + bDst[v], bSrc[v] + ko);
            CP_COMMIT();
        }

        const uint32_t sb = smemBase + (it & 3) * STAGE_B;
#pragma unroll
        for (int ks = 0; ks < 2; ks++) {
            uint32_t af[4][4];
            uint32_t bf[8][2];
#pragma unroll
            for (int am = 0; am < 4; am++)
                ldsm4(af[am][0], af[am][1], af[am][2], af[am][3],
                      sb + aBase[am] + ks * 4096);
#pragma unroll
            for (int bp = 0; bp < 4; bp++)
                ldsm4(bf[2 * bp][0], bf[2 * bp][1], bf[2 * bp + 1][0],
                      bf[2 * bp + 1][1], sb + bBase[bp] + ks * 8192);
#pragma unroll
            for (int am = 0; am < 4; am++)
#pragma unroll
                for (int bn = 0; bn < 8; bn++)
                    mma_bf16(acc[am][bn], af[am], bf[bn]);
        }
    }

    // Epilogue: exp(cos/tau), weight by pos, per-row reduce
#pragma unroll
    for (int am = 0; am < 4; am++) {
        int rloc0 = wm * 64 + am * 16 + (lane >> 2);
        int row0 = rowBase + rloc0;
        float ii0 = g_inv0[row0] * TAU_INV;
        float ii1 = g_inv0[row0 + 8] * TAU_INV;
        float s0 = 0.0f, p0 = 0.0f, s1 = 0.0f, p1 = 0.0f;
#pragma unroll
        for (int bn = 0; bn < 8; bn++) {
            int col = colBase + wn * 64 + bn * 8 + ((lane & 3) << 1);
            float j0 = g_inv1[col];
            float j1 = g_inv1[col + 1];
            float2 pv0 = *reinterpret_cast<const float2*>(
                &pos[(size_t)row0 * NDIM + col]);
            float2 pv1 = *reinterpret_cast<const float2*>(
                &pos[(size_t)(row0 + 8) * NDIM + col]);
            float m;
            m = expf(acc[am][bn][0] * ii0 * j0); s0 += m; p0 += m * pv0.x;
            m = expf(acc[am][bn][1] * ii0 * j1); s0 += m; p0 += m * pv0.y;
            m = expf(acc[am][bn][2] * ii1 * j0); s1 += m; p1 += m * pv1.x;
            m = expf(acc[am][bn][3] * ii1 * j1); s1 += m; p1 += m * pv1.y;
        }
#pragma unroll
        for (int off = 1; off < 4; off <<= 1) {
            s0 += __shfl_xor_sync(0xffffffffu, s0, off);
            p0 += __shfl_xor_sync(0xffffffffu, p0, off);
            s1 += __shfl_xor_sync(0xffffffffu, s1, off);
            p1 += __shfl_xor_sync(0xffffffffu, p1, off);
        }
        if ((lane & 3) == 0) {
            atomicAdd(&sS[rloc0], s0);
            atomicAdd(&sP[rloc0], p0);
            atomicAdd(&sS[rloc0 + 8], s1);
            atomicAdd(&sP[rloc0 + 8], p1);
        }
    }
    __syncthreads();
    if (t < SBM) {
        atomicAdd(&g_S[rowBase + t], sS[t]);
        atomicAdd(&g_P[rowBase + t], sP[t]);
    }
}

// ---------------------------------------------------------------------------
// Final loss: -mean(log(P/(S+eps)+eps))
// ---------------------------------------------------------------------------
__global__ void loss_kernel(float* __restrict__ loss_out)
{
    float local = 0.0f;
    for (int i = threadIdx.x; i < NDIM; i += 256) {
        local += logf(g_P[i] / (g_S[i] + EPSV) + EPSV);
    }
#pragma unroll
    for (int off = 16; off; off >>= 1)
        local += __shfl_xor_sync(0xffffffffu, local, off);

    __shared__ float sred[8];
    if ((threadIdx.x & 31) == 0) sred[threadIdx.x >> 5] = local;
    __syncthreads();
    if (threadIdx.x == 0) {
        float tot = 0.0f;
#pragma unroll
        for (int w = 0; w < 8; w++) tot += sred[w];
        loss_out[0] = -tot / (float)NDIM;
    }
}

// ---------------------------------------------------------------------------
// kernel_launch — inputs: embd0, embd1, pos, W1, b1, W2, b2
// output layout: [z0 (N*H) | z1 (N*H) | loss (1)]
// ---------------------------------------------------------------------------
extern "C" void kernel_launch(void* const* d_in, const int* in_sizes, int n_in,
                              void* d_out, int out_size)
{
    const float* embd0 = (const float*)d_in[0];
    const float* embd1 = (const float*)d_in[1];
    const float* pos   = (const float*)d_in[2];
    const float* W1    = (const float*)d_in[3];
    const float* b1    = (const float*)d_in[4];
    const float* W2    = (const float*)d_in[5];
    const float* b2    = (const float*)d_in[6];

    float* out = (float*)d_out;
    float* z0 = out;
    float* z1 = out + (size_t)NDIM * HDIM;
    float* loss = out + 2ull * NDIM * HDIM;

    float* h = nullptr;
    cudaGetSymbolAddress((void**)&h, g_h);
    float* h0 = h;
    float* h1 = h + (size_t)NDIM * HDIM;

    static bool attrDone = false;
    if (!attrDone) {
        cudaFuncSetAttribute(sim_fused_bf16,
                             cudaFuncAttributeMaxDynamicSharedMemorySize,
                             SIM_DSMEM);
        cudaFuncSetAttribute(gemm_bias_act_mma,
                             cudaFuncAttributeMaxDynamicSharedMemorySize,
                             MLP_SMEM);
        attrDone = true;
    }

    dim3 blk(NTHREADS);
    dim3 grid_mlp(HDIM / BN, NDIM / BM, 2);     // 4 x 64 x 2
    dim3 grid_sim(NDIM / SBN, NDIM / SBM);      // 32 x 64

    gemm_bias_act_mma<<<grid_mlp, blk, MLP_SMEM>>>(embd0, embd1, W1, b1, h0, h1,
                                                   HDIM, HDIM, 1);
    gemm_bias_act_mma<<<grid_mlp, blk, MLP_SMEM>>>(h0, h1, W2, b2, z0, z1,
                                                   HDIM, HDIM, 0);
    norm_init_kernel<<<2 * NDIM, 128>>>(z0, z1);
    sim_fused_bf16<<<grid_sim, blk, SIM_DSMEM>>>(pos);
    loss_kernel<<<1, 256>>>(loss);
}

// round 15
// speedup vs baseline: 1.0508x; 1.0508x over previous
#include <cuda_runtime.h>
#include <cuda_bf16.h>
#include <math.h>
#include <stdint.h>

// Problem constants
#define NDIM 8192
#define HDIM 512
#define TAU_INV 2.0f     // 1/0.5
#define EPSV 1e-8f

// MLP tiling (tf32 mma, double-buffered; unchanged)
constexpr int BM = 128, BN = 128, BK = 32;
constexpr int NTHREADS = 256;
constexpr int MLP_SMEM = 4 * 4096 * 4;     // 64 KB

// Sim tiling (fp8 e4m3 m16n8k32 + cp.async + ldmatrix):
// block 128x256, warp 64x64, SBK=64 fp8 elements, 4-stage pipeline.
constexpr int SBM = 128, SBN = 256, SBK = 64;
constexpr int STAGES = 4;
constexpr int A_STAGE_B = SBM * SBK;       // 8192 bytes (fp8 = 1 B/elt)
constexpr int B_STAGE_B = SBN * SBK;       // 16384 bytes
constexpr int STAGE_B = A_STAGE_B + B_STAGE_B;   // 24576
constexpr int SIM_DSMEM = STAGES * STAGE_B + 2 * SBM * 4;   // 99328

// Scratch (static device memory; no allocation allowed)
__device__ float g_h[2ull * NDIM * HDIM];       // hidden activations (32 MB)
__device__ unsigned char g_z0q[(size_t)NDIM * HDIM]; // e4m3 z0 (4 MB)
__device__ unsigned char g_z1q[(size_t)NDIM * HDIM]; // e4m3 z1 (4 MB)
__device__ float g_inv0[NDIM];
__device__ float g_inv1[NDIM];
__device__ float g_S[NDIM];
__device__ float g_P[NDIM];

__device__ __forceinline__ uint32_t smem_u32(const void* p) {
    uint32_t a;
    asm("{ .reg .u64 t; cvta.to.shared.u64 t, %1; cvt.u32.u64 %0, t; }"
        : "=r"(a) : "l"(p));
    return a;
}

__device__ __forceinline__ uint32_t f2tf32(float f) {
    uint32_t u;
    asm("cvt.rna.tf32.f32 %0, %1;" : "=r"(u) : "f"(f));
    return u;
}

// Pack 4 floats (k..k+3) into 4 e4m3 bytes, little-endian in k.
__device__ __forceinline__ uint32_t pack_e4m3_4(float x, float y, float z, float w) {
    uint16_t lo, hi;
    asm("cvt.rn.satfinite.e4m3x2.f32 %0, %1, %2;" : "=h"(lo) : "f"(y), "f"(x));
    asm("cvt.rn.satfinite.e4m3x2.f32 %0, %1, %2;" : "=h"(hi) : "f"(w), "f"(z));
    return (uint32_t)lo | ((uint32_t)hi << 16);
}

__device__ __forceinline__ void mma_tf32(float c[4],
                                         const uint32_t a[4],
                                         const uint32_t b[2]) {
    asm volatile(
        "mma.sync.aligned.m16n8k8.row.col.f32.tf32.tf32.f32 "
        "{%0,%1,%2,%3}, {%4,%5,%6,%7}, {%8,%9}, {%0,%1,%2,%3};"
        : "+f"(c[0]), "+f"(c[1]), "+f"(c[2]), "+f"(c[3])
        : "r"(a[0]), "r"(a[1]), "r"(a[2]), "r"(a[3]),
          "r"(b[0]), "r"(b[1]));
}

__device__ __forceinline__ void mma_fp8(float c[4],
                                        const uint32_t a[4],
                                        const uint32_t b[2]) {
    asm volatile(
        "mma.sync.aligned.m16n8k32.row.col.f32.e4m3.e4m3.f32 "
        "{%0,%1,%2,%3}, {%4,%5,%6,%7}, {%8,%9}, {%0,%1,%2,%3};"
        : "+f"(c[0]), "+f"(c[1]), "+f"(c[2]), "+f"(c[3])
        : "r"(a[0]), "r"(a[1]), "r"(a[2]), "r"(a[3]),
          "r"(b[0]), "r"(b[1]));
}

__device__ __forceinline__ void cp16(uint32_t dst, const void* src) {
    asm volatile("cp.async.cg.shared.global [%0], [%1], 16;"
                 :: "r"(dst), "l"(src) : "memory");
}
#define CP_COMMIT() asm volatile("cp.async.commit_group;" ::: "memory")
#define CP_WAIT(n)  asm volatile("cp.async.wait_group %0;" :: "n"(n) : "memory")

__device__ __forceinline__ void ldsm4(uint32_t& r0, uint32_t& r1,
                                      uint32_t& r2, uint32_t& r3, uint32_t a) {
    asm volatile("ldmatrix.sync.aligned.m8n8.x4.shared.b16 {%0,%1,%2,%3}, [%4];"
                 : "=r"(r0), "=r"(r1), "=r"(r2), "=r"(r3) : "r"(a));
}

// ---------------------------------------------------------------------------
// MLP GEMM (tf32 mma, double-buffered; unchanged from R11/R14)
// ---------------------------------------------------------------------------
__global__ __launch_bounds__(NTHREADS, 1) void gemm_bias_act_mma(
    const float* __restrict__ A0, const float* __restrict__ A1,
    const float* __restrict__ B, const float* __restrict__ bias,
    float* __restrict__ C0, float* __restrict__ C1,
    int K, int Nn, int doElu)
{
    extern __shared__ uint32_t msm[];
    uint32_t* sAb[2] = { msm, msm + 4096 };
    uint32_t* sBb[2] = { msm + 8192, msm + 12288 };

    const float* A = (blockIdx.z == 0) ? A0 : A1;
    float* C = (blockIdx.z == 0) ? C0 : C1;

    const int t = threadIdx.x;
    const int wid = t >> 5, lane = t & 31;
    const int wm = wid >> 2, wn = wid & 3;
    const int rowBase = blockIdx.y * BM;
    const int colBase = blockIdx.x * BN;

    uint32_t offA[4], offB[4];
    const float *gAp[4], *gBp[4];
#pragma unroll
    for (int v = 0; v < 4; v++) {
        int idx = t + v * 256;
        int row = idx >> 3;
        int q   = idx & 7;
        int ks  = q >> 1;
        int e2  = q & 1;
        int mt = row >> 4;
        int rr = row & 15;
        int r  = (rr >> 3) + (e2 << 1);
        offA[v] = (uint32_t)((((((mt << 2) + ks) << 5) + ((rr & 7) << 2)) << 2) + r);
        gAp[v] = A + (size_t)(rowBase + row) * K + (q << 2);
        int nt = row >> 3;
        offB[v] = (uint32_t)((((((nt << 2) + ks) << 5) + ((row & 7) << 2)) << 1) + e2);
        gBp[v] = B + (size_t)(colBase + row) * K + (q << 2);
    }

    float acc[4][4][4];
#pragma unroll
    for (int i = 0; i < 4; i++)
#pragma unroll
        for (int j = 0; j < 4; j++)
#pragma unroll
            for (int r = 0; r < 4; r++) acc[i][j][r] = 0.0f;

    {
#pragma unroll
        for (int v = 0; v < 4; v++) {
            float4 va = *reinterpret_cast<const float4*>(gAp[v]);
            uint32_t* p = &sAb[0][offA[v]];
            p[0]  = f2tf32(va.x); p[4]  = f2tf32(va.y);
            p[8]  = f2tf32(va.z); p[12] = f2tf32(va.w);
            float4 vb = *reinterpret_cast<const float4*>(gBp[v]);
            uint32_t* q2 = &sBb[0][offB[v]];
            q2[0] = f2tf32(vb.x); q2[2] = f2tf32(vb.y);
            q2[4] = f2tf32(vb.z); q2[6] = f2tf32(vb.w);
        }
    }
    __syncthreads();

    const int NITER = K / BK;   // 16
    for (int it = 0; it < NITER; it++) {
        const int cur = it & 1;
        const uint32_t* cA = sAb[cur];
        const uint32_t* cB = sBb[cur];
        const bool pf = (it + 1 < NITER);

        float4 fa[4], fb[4];
        if (pf) {
            const int kn = (it + 1) * BK;
#pragma unroll
            for (int v = 0; v < 4; v++) {
                fa[v] = *reinterpret_cast<const float4*>(gAp[v] + kn);
                fb[v] = *reinterpret_cast<const float4*>(gBp[v] + kn);
            }
        }

#pragma unroll
        for (int ks = 0; ks < 4; ks++) {
            uint32_t af[4][4];
            uint32_t bf[4][2];
#pragma unroll
            for (int am = 0; am < 4; am++) {
                uint4 v = *reinterpret_cast<const uint4*>(
                    &cA[(((((wm << 2) + am) << 2) + ks) << 5 | lane) << 2]);
                af[am][0] = v.x; af[am][1] = v.y; af[am][2] = v.z; af[am][3] = v.w;
            }
#pragma unroll
            for (int bn = 0; bn < 4; bn++) {
                uint2 v = *reinterpret_cast<const uint2*>(
                    &cB[(((((wn << 2) + bn) << 2) + ks) << 5 | lane) << 1]);
                bf[bn][0] = v.x; bf[bn][1] = v.y;
            }
#pragma unroll
            for (int am = 0; am < 4; am++)
#pragma unroll
                for (int bn = 0; bn < 4; bn++)
                    mma_tf32(acc[am][bn], af[am], bf[bn]);
        }

        if (pf) {
            uint32_t* dA = sAb[cur ^ 1];
            uint32_t* dB = sBb[cur ^ 1];
#pragma unroll
            for (int v = 0; v < 4; v++) {
                uint32_t* p = &dA[offA[v]];
                p[0]  = f2tf32(fa[v].x); p[4]  = f2tf32(fa[v].y);
                p[8]  = f2tf32(fa[v].z); p[12] = f2tf32(fa[v].w);
                uint32_t* q2 = &dB[offB[v]];
                q2[0] = f2tf32(fb[v].x); q2[2] = f2tf32(fb[v].y);
                q2[4] = f2tf32(fb[v].z); q2[6] = f2tf32(fb[v].w);
            }
        }
        __syncthreads();
    }

#pragma unroll
    for (int am = 0; am < 4; am++) {
        int row0 = rowBase + wm * 64 + am * 16 + (lane >> 2);
#pragma unroll
        for (int bn = 0; bn < 4; bn++) {
            int col = colBase + wn * 32 + bn * 8 + ((lane & 3) << 1);
            float b0 = bias[col], b1 = bias[col + 1];
            float v0 = acc[am][bn][0] + b0;
            float v1 = acc[am][bn][1] + b1;
            float v2 = acc[am][bn][2] + b0;
            float v3 = acc[am][bn][3] + b1;
            if (doElu) {
                v0 = (v0 > 0.0f) ? v0 : expm1f(v0);
                v1 = (v1 > 0.0f) ? v1 : expm1f(v1);
                v2 = (v2 > 0.0f) ? v2 : expm1f(v2);
                v3 = (v3 > 0.0f) ? v3 : expm1f(v3);
            }
            float2 lo = {v0, v1}, hi = {v2, v3};
            *reinterpret_cast<float2*>(&C[(size_t)row0 * Nn + col]) = lo;
            *reinterpret_cast<float2*>(&C[(size_t)(row0 + 8) * Nn + col]) = hi;
        }
    }
}

// ---------------------------------------------------------------------------
// Row norms (inverse) + zero S/P accumulators + emit e4m3 copies of z0/z1.
// ---------------------------------------------------------------------------
__global__ void norm_init_kernel(const float* __restrict__ z0,
                                 const float* __restrict__ z1)
{
    int b = blockIdx.x;
    int row = (b < NDIM) ? b : (b - NDIM);
    const float* z = (b < NDIM) ? z0 : z1;
    unsigned char* zq = (b < NDIM) ? g_z0q : g_z1q;

    float4 v = *reinterpret_cast<const float4*>(
        &z[(size_t)row * HDIM + threadIdx.x * 4]);

    // e4m3 copy: 4 floats -> 4 bytes
    uint32_t packed = pack_e4m3_4(v.x, v.y, v.z, v.w);
    reinterpret_cast<uint32_t*>(&zq[(size_t)row * HDIM])[threadIdx.x] = packed;

    float ss = v.x * v.x + v.y * v.y + v.z * v.z + v.w * v.w;
#pragma unroll
    for (int off = 16; off; off >>= 1)
        ss += __shfl_xor_sync(0xffffffffu, ss, off);

    __shared__ float sred[4];
    if ((threadIdx.x & 31) == 0) sred[threadIdx.x >> 5] = ss;
    __syncthreads();
    if (threadIdx.x == 0) {
        float tot = sred[0] + sred[1] + sred[2] + sred[3];
        float inv = 1.0f / sqrtf(tot);
        if (b < NDIM) {
            g_inv0[row] = inv;
            g_S[row] = 0.0f;
            g_P[row] = 0.0f;
        } else {
            g_inv1[row] = inv;
        }
    }
}

// ---------------------------------------------------------------------------
// Fused similarity: fp8 e4m3 m16n8k32, cp.async 4-stage, ldmatrix frags.
// smem per stage: A planes [kc∈0..3][row 0..127]*16B (8KB, kc=k/16) then
//                 B planes [kc][n 0..255]*16B (16KB). SBK=64 fp8 elems.
// ---------------------------------------------------------------------------
__global__ __launch_bounds__(NTHREADS, 1) void sim_fused_fp8(
    const float* __restrict__ pos)
{
    extern __shared__ uint32_t dynsmem[];
    const uint32_t smemBase = smem_u32(dynsmem);
    float* sS = (float*)((char*)dynsmem + STAGES * STAGE_B);
    float* sP = sS + SBM;

    const int t = threadIdx.x;
    const int wid = t >> 5, lane = t & 31;
    const int wm = wid >> 2, wn = wid & 3;
    const int rowBase = blockIdx.y * SBM;
    const int colBase = blockIdx.x * SBN;

    if (t < SBM) { sS[t] = 0.0f; sP[t] = 0.0f; }

    // Producer chunk descriptors. A: 2 chunks/thread, B: 4 chunks/thread.
    const unsigned char* aSrc[2]; uint32_t aDst[2];
    const unsigned char* bSrc[4]; uint32_t bDst[4];
#pragma unroll
    for (int v = 0; v < 2; v++) {
        int idx = t + v * 256;
        int row = idx & 127, kc = idx >> 7;     // kc in 0..3 (k/16)
        aDst[v] = (uint32_t)(kc * 2048 + row * 16);
        aSrc[v] = g_z0q + (size_t)(rowBase + row) * HDIM + kc * 16;
    }
#pragma unroll
    for (int v = 0; v < 4; v++) {
        int idx = t + v * 256;
        int n = idx & 255, kc = idx >> 8;       // kc in 0..3
        bDst[v] = (uint32_t)(A_STAGE_B + kc * 4096 + n * 16);
        bSrc[v] = g_z1q + (size_t)(colBase + n) * HDIM + kc * 16;
    }

    // ldmatrix per-lane addresses (identical byte geometry to bf16 version).
    const int gq = lane >> 3, rig = lane & 7;
    uint32_t aBase[4], bBase[4];
#pragma unroll
    for (int am = 0; am < 4; am++)
        aBase[am] = (uint32_t)((gq >> 1) * 2048
                    + (wm * 64 + am * 16 + ((gq & 1) << 3) + rig) * 16);
#pragma unroll
    for (int bp = 0; bp < 4; bp++)
        bBase[bp] = (uint32_t)(A_STAGE_B + (gq & 1) * 4096
                    + (wn * 64 + bp * 16 + ((gq >> 1) << 3) + rig) * 16);

    float acc[4][8][4];
#pragma unroll
    for (int i = 0; i < 4; i++)
#pragma unroll
        for (int j = 0; j < 8; j++)
#pragma unroll
            for (int r = 0; r < 4; r++) acc[i][j][r] = 0.0f;

    // Prologue: issue stages 0..2
#pragma unroll
    for (int s = 0; s < STAGES - 1; s++) {
        uint32_t sb = smemBase + s * STAGE_B;
        int ko = s * SBK;   // fp8: bytes == elements
#pragma unroll
        for (int v = 0; v < 2; v++) cp16(sb + aDst[v], aSrc[v] + ko);
#pragma unroll
        for (int v = 0; v < 4; v++) cp16(sb + bDst[v], bSrc[v] + ko);
        CP_COMMIT();
    }

    const int NITER = HDIM / SBK;   // 8
    for (int it = 0; it < NITER; it++) {
        if (it < NITER - 2)      CP_WAIT(2);
        else if (it == NITER - 2) CP_WAIT(1);
        else                      CP_WAIT(0);
        __syncthreads();

        if (it + STAGES - 1 < NITER) {
            int s = it + STAGES - 1;
            uint32_t sb = smemBase + (s & 3) * STAGE_B;
            int ko = s * SBK;
#pragma unroll
            for (int v = 0; v < 2; v++) cp16(sb + aDst[v], aSrc[v] + ko);
#pragma unroll
            for (int v = 0; v < 4; v++) cp16(sb + bDst[v], bSrc[v] + ko);
            CP_COMMIT();
        }

        const uint32_t sb = smemBase + (it & 3) * STAGE_B;
#pragma unroll
        for (int ks = 0; ks < 2; ks++) {      // k32 steps within SBK=64
            uint32_t af[4][4];
            uint32_t bf[8][2];
#pragma unroll
            for (int am = 0; am < 4; am++)
                ldsm4(af[am][0], af[am][1], af[am][2], af[am][3],
                      sb + aBase[am] + ks * 4096);
#pragma unroll
            for (int bp = 0; bp < 4; bp++)
                ldsm4(bf[2 * bp][0], bf[2 * bp][1], bf[2 * bp + 1][0],
                      bf[2 * bp + 1][1], sb + bBase[bp] + ks * 8192);
#pragma unroll
            for (int am = 0; am < 4; am++)
#pragma unroll
                for (int bn = 0; bn < 8; bn++)
                    mma_fp8(acc[am][bn], af[am], bf[bn]);
        }
    }

    // Epilogue: exp(cos/tau), weight by pos, per-row reduce
#pragma unroll
    for (int am = 0; am < 4; am++) {
        int rloc0 = wm * 64 + am * 16 + (lane >> 2);
        int row0 = rowBase + rloc0;
        float ii0 = g_inv0[row0] * TAU_INV;
        float ii1 = g_inv0[row0 + 8] * TAU_INV;
        float s0 = 0.0f, p0 = 0.0f, s1 = 0.0f, p1 = 0.0f;
#pragma unroll
        for (int bn = 0; bn < 8; bn++) {
            int col = colBase + wn * 64 + bn * 8 + ((lane & 3) << 1);
            float j0 = g_inv1[col];
            float j1 = g_inv1[col + 1];
            float2 pv0 = *reinterpret_cast<const float2*>(
                &pos[(size_t)row0 * NDIM + col]);
            float2 pv1 = *reinterpret_cast<const float2*>(
                &pos[(size_t)(row0 + 8) * NDIM + col]);
            float m;
            m = expf(acc[am][bn][0] * ii0 * j0); s0 += m; p0 += m * pv0.x;
            m = expf(acc[am][bn][1] * ii0 * j1); s0 += m; p0 += m * pv0.y;
            m = expf(acc[am][bn][2] * ii1 * j0); s1 += m; p1 += m * pv1.x;
            m = expf(acc[am][bn][3] * ii1 * j1); s1 += m; p1 += m * pv1.y;
        }
#pragma unroll
        for (int off = 1; off < 4; off <<= 1) {
            s0 += __shfl_xor_sync(0xffffffffu, s0, off);
            p0 += __shfl_xor_sync(0xffffffffu, p0, off);
            s1 += __shfl_xor_sync(0xffffffffu, s1, off);
            p1 += __shfl_xor_sync(0xffffffffu, p1, off);
        }
        if ((lane & 3) == 0) {
            atomicAdd(&sS[rloc0], s0);
            atomicAdd(&sP[rloc0], p0);
            atomicAdd(&sS[rloc0 + 8], s1);
            atomicAdd(&sP[rloc0 + 8], p1);
        }
    }
    __syncthreads();
    if (t < SBM) {
        atomicAdd(&g_S[rowBase + t], sS[t]);
        atomicAdd(&g_P[rowBase + t], sP[t]);
    }
}

// ---------------------------------------------------------------------------
// Final loss: -mean(log(P/(S+eps)+eps))
// ---------------------------------------------------------------------------
__global__ void loss_kernel(float* __restrict__ loss_out)
{
    float local = 0.0f;
    for (int i = threadIdx.x; i < NDIM; i += 256) {
        local += logf(g_P[i] / (g_S[i] + EPSV) + EPSV);
    }
#pragma unroll
    for (int off = 16; off; off >>= 1)
        local += __shfl_xor_sync(0xffffffffu, local, off);

    __shared__ float sred[8];
    if ((threadIdx.x & 31) == 0) sred[threadIdx.x >> 5] = local;
    __syncthreads();
    if (threadIdx.x == 0) {
        float tot = 0.0f;
#pragma unroll
        for (int w = 0; w < 8; w++) tot += sred[w];
        loss_out[0] = -tot / (float)NDIM;
    }
}

// ---------------------------------------------------------------------------
// kernel_launch — inputs: embd0, embd1, pos, W1, b1, W2, b2
// output layout: [z0 (N*H) | z1 (N*H) | loss (1)]
// ---------------------------------------------------------------------------
extern "C" void kernel_launch(void* const* d_in, const int* in_sizes, int n_in,
                              void* d_out, int out_size)
{
    const float* embd0 = (const float*)d_in[0];
    const float* embd1 = (const float*)d_in[1];
    const float* pos   = (const float*)d_in[2];
    const float* W1    = (const float*)d_in[3];
    const float* b1    = (const float*)d_in[4];
    const float* W2    = (const float*)d_in[5];
    const float* b2    = (const float*)d_in[6];

    float* out = (float*)d_out;
    float* z0 = out;
    float* z1 = out + (size_t)NDIM * HDIM;
    float* loss = out + 2ull * NDIM * HDIM;

    float* h = nullptr;
    cudaGetSymbolAddress((void**)&h, g_h);
    float* h0 = h;
    float* h1 = h + (size_t)NDIM * HDIM;

    static bool attrDone = false;
    if (!attrDone) {
        cudaFuncSetAttribute(sim_fused_fp8,
                             cudaFuncAttributeMaxDynamicSharedMemorySize,
                             SIM_DSMEM);
        cudaFuncSetAttribute(gemm_bias_act_mma,
                             cudaFuncAttributeMaxDynamicSharedMemorySize,
                             MLP_SMEM);
        attrDone = true;
    }

    dim3 blk(NTHREADS);
    dim3 grid_mlp(HDIM / BN, NDIM / BM, 2);     // 4 x 64 x 2
    dim3 grid_sim(NDIM / SBN, NDIM / SBM);      // 32 x 64

    gemm_bias_act_mma<<<grid_mlp, blk, MLP_SMEM>>>(embd0, embd1, W1, b1, h0, h1,
                                                   HDIM, HDIM, 1);
    gemm_bias_act_mma<<<grid_mlp, blk, MLP_SMEM>>>(h0, h1, W2, b2, z0, z1,
                                                   HDIM, HDIM, 0);
    norm_init_kernel<<<2 * NDIM, 128>>>(z0, z1);
    sim_fused_fp8<<<grid_sim, blk, SIM_DSMEM>>>(pos);
    loss_kernel<<<1, 256>>>(loss);
}

// round 16
// speedup vs baseline: 1.0693x; 1.0176x over previous
#include <cuda_runtime.h>
#include <cuda_bf16.h>
#include <math.h>
#include <stdint.h>

// Problem constants
#define NDIM 8192
#define HDIM 512
#define TAU_INV 2.0f     // 1/0.5
#define EPSV 1e-8f

// MLP tiling (tf32 mma, double-buffered)
constexpr int BM = 128, BN = 128, BK = 32;
constexpr int NTHREADS = 256;
constexpr int MLP_SMEM = 4 * 4096 * 4 + BM * 4;   // 2x(A+B) bufs + row-sumsq

// Sim tiling (bf16 m16n8k16, R11 structure): block 128x256, warp 64x64,
// BK=32, double-buffered, LDG-early/STS-late.
constexpr int SBM = 128, SBN = 256, SBK = 32;
constexpr int SA_WORDS = SBM * SBK / 2;   // 2048 uint32 per stage
constexpr int SB_WORDS = SBN * SBK / 2;   // 4096 uint32 per stage
constexpr int SIM_DSMEM = (2 * SA_WORDS + 2 * SB_WORDS) * 4 + 2 * SBM * 4;

// Scratch (static device memory; no allocation allowed)
__device__ float g_h[2ull * NDIM * HDIM];            // hidden activations (32 MB)
__device__ __nv_bfloat16 g_z0b[(size_t)NDIM * HDIM]; // bf16 z0 (8 MB)
__device__ __nv_bfloat16 g_z1b[(size_t)NDIM * HDIM]; // bf16 z1 (8 MB)
__device__ float g_inv0[NDIM];   // accumulates sum(z0^2), then holds 1/norm
__device__ float g_inv1[NDIM];
__device__ float g_S[NDIM];
__device__ float g_P[NDIM];

__device__ __forceinline__ uint32_t f2tf32(float f) {
    uint32_t u;
    asm("cvt.rna.tf32.f32 %0, %1;" : "=r"(u) : "f"(f));
    return u;
}

__device__ __forceinline__ void mma_tf32(float c[4],
                                         const uint32_t a[4],
                                         const uint32_t b[2]) {
    asm volatile(
        "mma.sync.aligned.m16n8k8.row.col.f32.tf32.tf32.f32 "
        "{%0,%1,%2,%3}, {%4,%5,%6,%7}, {%8,%9}, {%0,%1,%2,%3};"
        : "+f"(c[0]), "+f"(c[1]), "+f"(c[2]), "+f"(c[3])
        : "r"(a[0]), "r"(a[1]), "r"(a[2]), "r"(a[3]),
          "r"(b[0]), "r"(b[1]));
}

__device__ __forceinline__ void mma_bf16(float c[4],
                                         const uint32_t a[4],
                                         const uint32_t b[2]) {
    asm volatile(
        "mma.sync.aligned.m16n8k16.row.col.f32.bf16.bf16.f32 "
        "{%0,%1,%2,%3}, {%4,%5,%6,%7}, {%8,%9}, {%0,%1,%2,%3};"
        : "+f"(c[0]), "+f"(c[1]), "+f"(c[2]), "+f"(c[3])
        : "r"(a[0]), "r"(a[1]), "r"(a[2]), "r"(a[3]),
          "r"(b[0]), "r"(b[1]));
}

// ---------------------------------------------------------------------------
// MLP GEMM: C = act(A @ B^T + bias), tf32 mma, double-buffered pipeline.
// doElu==1 (layer 1): also zeroes g_inv/g_S/g_P via the x==0,z==0 blocks.
// doElu==0 (layer 2): epilogue additionally emits bf16 z copy and accumulates
//                     per-row sum(z^2) into g_inv0/g_inv1.
// ---------------------------------------------------------------------------
__global__ __launch_bounds__(NTHREADS, 1) void gemm_bias_act_mma(
    const float* __restrict__ A0, const float* __restrict__ A1,
    const float* __restrict__ B, const float* __restrict__ bias,
    float* __restrict__ C0, float* __restrict__ C1,
    int K, int Nn, int doElu)
{
    extern __shared__ uint32_t msm[];
    uint32_t* sAb[2] = { msm, msm + 4096 };
    uint32_t* sBb[2] = { msm + 8192, msm + 12288 };
    float* sRow = (float*)(msm + 16384);   // [BM] per-row sumsq (layer 2)

    const float* A = (blockIdx.z == 0) ? A0 : A1;
    float* C = (blockIdx.z == 0) ? C0 : C1;
    __nv_bfloat16* Cb = (blockIdx.z == 0) ? g_z0b : g_z1b;
    float* gSS = (blockIdx.z == 0) ? g_inv0 : g_inv1;

    const int t = threadIdx.x;
    const int wid = t >> 5, lane = t & 31;
    const int wm = wid >> 2, wn = wid & 3;
    const int rowBase = blockIdx.y * BM;
    const int colBase = blockIdx.x * BN;

    // Layer-1 auxiliary: zero the accumulators (runs before layer 2 launch).
    if (doElu && blockIdx.x == 0 && blockIdx.z == 0) {
        int idx = blockIdx.y * NTHREADS + t;   // 64*256 = 16384 >= 8192
        if (idx < NDIM) {
            g_inv0[idx] = 0.0f; g_inv1[idx] = 0.0f;
            g_S[idx] = 0.0f;    g_P[idx] = 0.0f;
        }
    }
    if (!doElu && t < BM) sRow[t] = 0.0f;

    uint32_t offA[4], offB[4];
    const float *gAp[4], *gBp[4];
#pragma unroll
    for (int v = 0; v < 4; v++) {
        int idx = t + v * 256;
        int row = idx >> 3;
        int q   = idx & 7;
        int ks  = q >> 1;
        int e2  = q & 1;
        int mt = row >> 4;
        int rr = row & 15;
        int r  = (rr >> 3) + (e2 << 1);
        offA[v] = (uint32_t)((((((mt << 2) + ks) << 5) + ((rr & 7) << 2)) << 2) + r);
        gAp[v] = A + (size_t)(rowBase + row) * K + (q << 2);
        int nt = row >> 3;
        offB[v] = (uint32_t)((((((nt << 2) + ks) << 5) + ((row & 7) << 2)) << 1) + e2);
        gBp[v] = B + (size_t)(colBase + row) * K + (q << 2);
    }

    float acc[4][4][4];
#pragma unroll
    for (int i = 0; i < 4; i++)
#pragma unroll
        for (int j = 0; j < 4; j++)
#pragma unroll
            for (int r = 0; r < 4; r++) acc[i][j][r] = 0.0f;

    // Prologue: fill buffer 0 with k-chunk 0
    {
#pragma unroll
        for (int v = 0; v < 4; v++) {
            float4 va = *reinterpret_cast<const float4*>(gAp[v]);
            uint32_t* p = &sAb[0][offA[v]];
            p[0]  = f2tf32(va.x); p[4]  = f2tf32(va.y);
            p[8]  = f2tf32(va.z); p[12] = f2tf32(va.w);
            float4 vb = *reinterpret_cast<const float4*>(gBp[v]);
            uint32_t* q2 = &sBb[0][offB[v]];
            q2[0] = f2tf32(vb.x); q2[2] = f2tf32(vb.y);
            q2[4] = f2tf32(vb.z); q2[6] = f2tf32(vb.w);
        }
    }
    __syncthreads();

    const int NITER = K / BK;   // 16
    for (int it = 0; it < NITER; it++) {
        const int cur = it & 1;
        const uint32_t* cA = sAb[cur];
        const uint32_t* cB = sBb[cur];
        const bool pf = (it + 1 < NITER);

        float4 fa[4], fb[4];
        if (pf) {
            const int kn = (it + 1) * BK;
#pragma unroll
            for (int v = 0; v < 4; v++) {
                fa[v] = *reinterpret_cast<const float4*>(gAp[v] + kn);
                fb[v] = *reinterpret_cast<const float4*>(gBp[v] + kn);
            }
        }

#pragma unroll
        for (int ks = 0; ks < 4; ks++) {
            uint32_t af[4][4];
            uint32_t bf[4][2];
#pragma unroll
            for (int am = 0; am < 4; am++) {
                uint4 v = *reinterpret_cast<const uint4*>(
                    &cA[(((((wm << 2) + am) << 2) + ks) << 5 | lane) << 2]);
                af[am][0] = v.x; af[am][1] = v.y; af[am][2] = v.z; af[am][3] = v.w;
            }
#pragma unroll
            for (int bn = 0; bn < 4; bn++) {
                uint2 v = *reinterpret_cast<const uint2*>(
                    &cB[(((((wn << 2) + bn) << 2) + ks) << 5 | lane) << 1]);
                bf[bn][0] = v.x; bf[bn][1] = v.y;
            }
#pragma unroll
            for (int am = 0; am < 4; am++)
#pragma unroll
                for (int bn = 0; bn < 4; bn++)
                    mma_tf32(acc[am][bn], af[am], bf[bn]);
        }

        if (pf) {
            uint32_t* dA = sAb[cur ^ 1];
            uint32_t* dB = sBb[cur ^ 1];
#pragma unroll
            for (int v = 0; v < 4; v++) {
                uint32_t* p = &dA[offA[v]];
                p[0]  = f2tf32(fa[v].x); p[4]  = f2tf32(fa[v].y);
                p[8]  = f2tf32(fa[v].z); p[12] = f2tf32(fa[v].w);
                uint32_t* q2 = &dB[offB[v]];
                q2[0] = f2tf32(fb[v].x); q2[2] = f2tf32(fb[v].y);
                q2[4] = f2tf32(fb[v].z); q2[6] = f2tf32(fb[v].w);
            }
        }
        __syncthreads();
    }

    // Epilogue
#pragma unroll
    for (int am = 0; am < 4; am++) {
        int rloc0 = wm * 64 + am * 16 + (lane >> 2);
        int row0 = rowBase + rloc0;
        float ss0 = 0.0f, ss1 = 0.0f;
#pragma unroll
        for (int bn = 0; bn < 4; bn++) {
            int col = colBase + wn * 32 + bn * 8 + ((lane & 3) << 1);
            float b0 = bias[col], b1 = bias[col + 1];
            float v0 = acc[am][bn][0] + b0;
            float v1 = acc[am][bn][1] + b1;
            float v2 = acc[am][bn][2] + b0;
            float v3 = acc[am][bn][3] + b1;
            if (doElu) {
                v0 = (v0 > 0.0f) ? v0 : expm1f(v0);
                v1 = (v1 > 0.0f) ? v1 : expm1f(v1);
                v2 = (v2 > 0.0f) ? v2 : expm1f(v2);
                v3 = (v3 > 0.0f) ? v3 : expm1f(v3);
            }
            float2 lo = {v0, v1}, hi = {v2, v3};
            *reinterpret_cast<float2*>(&C[(size_t)row0 * Nn + col]) = lo;
            *reinterpret_cast<float2*>(&C[(size_t)(row0 + 8) * Nn + col]) = hi;
            if (!doElu) {
                // bf16 copy + per-row sumsq (layer 2 only)
                __nv_bfloat162 p0 = __floats2bfloat162_rn(v0, v1);
                __nv_bfloat162 p1 = __floats2bfloat162_rn(v2, v3);
                *reinterpret_cast<uint32_t*>(&Cb[(size_t)row0 * Nn + col]) =
                    *reinterpret_cast<uint32_t*>(&p0);
                *reinterpret_cast<uint32_t*>(&Cb[(size_t)(row0 + 8) * Nn + col]) =
                    *reinterpret_cast<uint32_t*>(&p1);
                ss0 += v0 * v0 + v1 * v1;
                ss1 += v2 * v2 + v3 * v3;
            }
        }
        if (!doElu) {
            // reduce over the 4 lanes of the quad (same row, different cols)
#pragma unroll
            for (int off = 1; off < 4; off <<= 1) {
                ss0 += __shfl_xor_sync(0xffffffffu, ss0, off);
                ss1 += __shfl_xor_sync(0xffffffffu, ss1, off);
            }
            if ((lane & 3) == 0) {
                atomicAdd(&sRow[rloc0], ss0);
                atomicAdd(&sRow[rloc0 + 8], ss1);
            }
        }
    }
    if (!doElu) {
        __syncthreads();
        if (t < BM) atomicAdd(&gSS[rowBase + t], sRow[t]);
    }
}

// ---------------------------------------------------------------------------
// norm_finish: convert accumulated sum(z^2) -> 1/norm.
// ---------------------------------------------------------------------------
__global__ void norm_finish_kernel()
{
    int idx = blockIdx.x * 256 + threadIdx.x;
    if (idx < NDIM) {
        g_inv0[idx] = rsqrtf(g_inv0[idx]);
        g_inv1[idx] = rsqrtf(g_inv1[idx]);
    }
}

// ---------------------------------------------------------------------------
// Fused similarity (bf16 m16n8k16): block 128x256, warp 64x64, BK=32,
// double-buffered; per iter: LDG(it+1) early -> mma(it) -> STS(it+1) -> sync.
// (R11 structure — best measured configuration.)
// ---------------------------------------------------------------------------
__global__ __launch_bounds__(NTHREADS, 1) void sim_fused_bf16(
    const float* __restrict__ pos)
{
    extern __shared__ uint32_t dynsmem[];
    uint32_t* sA = dynsmem;                          // [2][SA_WORDS]
    uint32_t* sB = dynsmem + 2 * SA_WORDS;           // [2][SB_WORDS]
    float* sS = (float*)(dynsmem + 2 * SA_WORDS + 2 * SB_WORDS);
    float* sP = sS + SBM;

    const int t = threadIdx.x;
    const int wid = t >> 5, lane = t & 31;
    const int wm = wid >> 2, wn = wid & 3;
    const int rowBase = blockIdx.y * SBM;
    const int colBase = blockIdx.x * SBN;

    if (t < SBM) { sS[t] = 0.0f; sP[t] = 0.0f; }

    uint32_t offA[2]; const __nv_bfloat16* gA[2];
    uint32_t offB[4]; const __nv_bfloat16* gB[4];
#pragma unroll
    for (int v = 0; v < 2; v++) {
        int idx = t + v * 256;
        int row = idx >> 2;
        int c   = idx & 3;
        int ks  = c >> 1;
        int hi  = c & 1;
        int mt  = row >> 4;
        int rr  = row & 15;
        offA[v] = (uint32_t)((((mt * 2 + ks) * 32 + (rr & 7) * 4) << 2)
                             + (rr >> 3) + (hi << 1));
        gA[v] = g_z0b + (size_t)(rowBase + row) * HDIM + c * 8;
    }
#pragma unroll
    for (int v = 0; v < 4; v++) {
        int idx = t + v * 256;
        int n   = idx >> 2;
        int c   = idx & 3;
        int ks  = c >> 1;
        int hi  = c & 1;
        int nt  = n >> 3;
        offB[v] = (uint32_t)((((nt * 2 + ks) * 32 + (n & 7) * 4) << 1) + hi);
        gB[v] = g_z1b + (size_t)(colBase + n) * HDIM + c * 8;
    }

    float acc[4][8][4];
#pragma unroll
    for (int i = 0; i < 4; i++)
#pragma unroll
        for (int j = 0; j < 8; j++)
#pragma unroll
            for (int r = 0; r < 4; r++) acc[i][j][r] = 0.0f;

    {
#pragma unroll
        for (int v = 0; v < 2; v++) {
            uint4 w = *reinterpret_cast<const uint4*>(gA[v]);
            uint32_t* p = &sA[offA[v]];
            p[0] = w.x; p[4] = w.y; p[8] = w.z; p[12] = w.w;
        }
#pragma unroll
        for (int v = 0; v < 4; v++) {
            uint4 w = *reinterpret_cast<const uint4*>(gB[v]);
            uint32_t* p = &sB[offB[v]];
            p[0] = w.x; p[2] = w.y; p[4] = w.z; p[6] = w.w;
        }
    }
    __syncthreads();

    const int NITER = HDIM / SBK;   // 16
    for (int it = 0; it < NITER; it++) {
        const int cur = it & 1;
        const uint32_t* cA = sA + cur * SA_WORDS;
        const uint32_t* cB = sB + cur * SB_WORDS;
        const bool pf = (it + 1 < NITER);

        uint4 wA[2], wB[4];
        if (pf) {
            const int kn = (it + 1) * SBK;
#pragma unroll
            for (int v = 0; v < 2; v++)
                wA[v] = *reinterpret_cast<const uint4*>(gA[v] + kn);
#pragma unroll
            for (int v = 0; v < 4; v++)
                wB[v] = *reinterpret_cast<const uint4*>(gB[v] + kn);
        }

#pragma unroll
        for (int ks = 0; ks < 2; ks++) {
            uint32_t af[4][4];
            uint32_t bf[8][2];
#pragma unroll
            for (int am = 0; am < 4; am++) {
                uint4 v = *reinterpret_cast<const uint4*>(
                    &cA[((((wm * 4 + am) * 2 + ks) * 32 + lane) << 2)]);
                af[am][0] = v.x; af[am][1] = v.y; af[am][2] = v.z; af[am][3] = v.w;
            }
#pragma unroll
            for (int bn = 0; bn < 8; bn++) {
                uint2 v = *reinterpret_cast<const uint2*>(
                    &cB[((((wn * 8 + bn) * 2 + ks) * 32 + lane) << 1)]);
                bf[bn][0] = v.x; bf[bn][1] = v.y;
            }
#pragma unroll
            for (int am = 0; am < 4; am++)
#pragma unroll
                for (int bn = 0; bn < 8; bn++)
                    mma_bf16(acc[am][bn], af[am], bf[bn]);
        }

        if (pf) {
            uint32_t* dA = sA + (cur ^ 1) * SA_WORDS;
            uint32_t* dB = sB + (cur ^ 1) * SB_WORDS;
#pragma unroll
            for (int v = 0; v < 2; v++) {
                uint32_t* p = &dA[offA[v]];
                p[0] = wA[v].x; p[4] = wA[v].y; p[8] = wA[v].z; p[12] = wA[v].w;
            }
#pragma unroll
            for (int v = 0; v < 4; v++) {
                uint32_t* p = &dB[offB[v]];
                p[0] = wB[v].x; p[2] = wB[v].y; p[4] = wB[v].z; p[6] = wB[v].w;
            }
        }
        __syncthreads();
    }

    // Epilogue: exp(cos/tau), weight by pos, per-row reduce
#pragma unroll
    for (int am = 0; am < 4; am++) {
        int rloc0 = wm * 64 + am * 16 + (lane >> 2);
        int row0 = rowBase + rloc0;
        float ii0 = g_inv0[row0] * TAU_INV;
        float ii1 = g_inv0[row0 + 8] * TAU_INV;
        float s0 = 0.0f, p0 = 0.0f, s1 = 0.0f, p1 = 0.0f;
#pragma unroll
        for (int bn = 0; bn < 8; bn++) {
            int col = colBase + wn * 64 + bn * 8 + ((lane & 3) << 1);
            float j0 = g_inv1[col];
            float j1 = g_inv1[col + 1];
            float2 pv0 = *reinterpret_cast<const float2*>(
                &pos[(size_t)row0 * NDIM + col]);
            float2 pv1 = *reinterpret_cast<const float2*>(
                &pos[(size_t)(row0 + 8) * NDIM + col]);
            float m;
            m = expf(acc[am][bn][0] * ii0 * j0); s0 += m; p0 += m * pv0.x;
            m = expf(acc[am][bn][1] * ii0 * j1); s0 += m; p0 += m * pv0.y;
            m = expf(acc[am][bn][2] * ii1 * j0); s1 += m; p1 += m * pv1.x;
            m = expf(acc[am][bn][3] * ii1 * j1); s1 += m; p1 += m * pv1.y;
        }
#pragma unroll
        for (int off = 1; off < 4; off <<= 1) {
            s0 += __shfl_xor_sync(0xffffffffu, s0, off);
            p0 += __shfl_xor_sync(0xffffffffu, p0, off);
            s1 += __shfl_xor_sync(0xffffffffu, s1, off);
            p1 += __shfl_xor_sync(0xffffffffu, p1, off);
        }
        if ((lane & 3) == 0) {
            atomicAdd(&sS[rloc0], s0);
            atomicAdd(&sP[rloc0], p0);
            atomicAdd(&sS[rloc0 + 8], s1);
            atomicAdd(&sP[rloc0 + 8], p1);
        }
    }
    __syncthreads();
    if (t < SBM) {
        atomicAdd(&g_S[rowBase + t], sS[t]);
        atomicAdd(&g_P[rowBase + t], sP[t]);
    }
}

// ---------------------------------------------------------------------------
// Final loss: -mean(log(P/(S+eps)+eps))
// ---------------------------------------------------------------------------
__global__ void loss_kernel(float* __restrict__ loss_out)
{
    float local = 0.0f;
    for (int i = threadIdx.x; i < NDIM; i += 256) {
        local += logf(g_P[i] / (g_S[i] + EPSV) + EPSV);
    }
#pragma unroll
    for (int off = 16; off; off >>= 1)
        local += __shfl_xor_sync(0xffffffffu, local, off);

    __shared__ float sred[8];
    if ((threadIdx.x & 31) == 0) sred[threadIdx.x >> 5] = local;
    __syncthreads();
    if (threadIdx.x == 0) {
        float tot = 0.0f;
#pragma unroll
        for (int w = 0; w < 8; w++) tot += sred[w];
        loss_out[0] = -tot / (float)NDIM;
    }
}

// ---------------------------------------------------------------------------
// kernel_launch — inputs: embd0, embd1, pos, W1, b1, W2, b2
// output layout: [z0 (N*H) | z1 (N*H) | loss (1)]
// ---------------------------------------------------------------------------
extern "C" void kernel_launch(void* const* d_in, const int* in_sizes, int n_in,
                              void* d_out, int out_size)
{
    const float* embd0 = (const float*)d_in[0];
    const float* embd1 = (const float*)d_in[1];
    const float* pos   = (const float*)d_in[2];
    const float* W1    = (const float*)d_in[3];
    const float* b1    = (const float*)d_in[4];
    const float* W2    = (const float*)d_in[5];
    const float* b2    = (const float*)d_in[6];

    float* out = (float*)d_out;
    float* z0 = out;
    float* z1 = out + (size_t)NDIM * HDIM;
    float* loss = out + 2ull * NDIM * HDIM;

    float* h = nullptr;
    cudaGetSymbolAddress((void**)&h, g_h);
    float* h0 = h;
    float* h1 = h + (size_t)NDIM * HDIM;

    static bool attrDone = false;
    if (!attrDone) {
        cudaFuncSetAttribute(sim_fused_bf16,
                             cudaFuncAttributeMaxDynamicSharedMemorySize,
                             SIM_DSMEM);
        cudaFuncSetAttribute(gemm_bias_act_mma,
                             cudaFuncAttributeMaxDynamicSharedMemorySize,
                             MLP_SMEM);
        attrDone = true;
    }

    dim3 blk(NTHREADS);
    dim3 grid_mlp(HDIM / BN, NDIM / BM, 2);     // 4 x 64 x 2
    dim3 grid_sim(NDIM / SBN, NDIM / SBM);      // 32 x 64

    // Layer 1 (ELU) — also zeroes g_inv*/g_S/g_P
    gemm_bias_act_mma<<<grid_mlp, blk, MLP_SMEM>>>(embd0, embd1, W1, b1, h0, h1,
                                                   HDIM, HDIM, 1);
    // Layer 2 (linear) — also emits bf16 copies + per-row sum(z^2)
    gemm_bias_act_mma<<<grid_mlp, blk, MLP_SMEM>>>(h0, h1, W2, b2, z0, z1,
                                                   HDIM, HDIM, 0);
    // sum(z^2) -> 1/norm
    norm_finish_kernel<<<NDIM / 256, 256>>>();
    // Fused similarity + row reductions
    sim_fused_bf16<<<grid_sim, blk, SIM_DSMEM>>>(pos);
    // Scalar loss
    loss_kernel<<<1, 256>>>(loss);
}

// round 17
// speedup vs baseline: 1.1638x; 1.0884x over previous
#include <cuda_runtime.h>
#include <cuda_bf16.h>
#include <math.h>
#include <stdint.h>

// Problem constants
#define NDIM 8192
#define HDIM 512
#define TAU_INV 2.0f     // 1/0.5
#define EPSV 1e-8f

// MLP tiling (tf32 mma, single-buffered static smem, 2 CTAs/SM)
constexpr int BM = 128, BN = 128, BK = 32;
constexpr int NTHREADS = 256;

// Sim tiling (bf16 m16n8k16, R11 structure): block 128x256, warp 64x64,
// BK=32, double-buffered, LDG-early/STS-late.
constexpr int SBM = 128, SBN = 256, SBK = 32;
constexpr int SA_WORDS = SBM * SBK / 2;   // 2048 uint32 per stage
constexpr int SB_WORDS = SBN * SBK / 2;   // 4096 uint32 per stage
constexpr int SIM_DSMEM = (2 * SA_WORDS + 2 * SB_WORDS) * 4 + 2 * SBM * 4;

// Scratch (static device memory; no allocation allowed)
__device__ float g_h[2ull * NDIM * HDIM];            // hidden activations (32 MB)
__device__ __nv_bfloat16 g_z0b[(size_t)NDIM * HDIM]; // bf16 z0 (8 MB)
__device__ __nv_bfloat16 g_z1b[(size_t)NDIM * HDIM]; // bf16 z1 (8 MB)
__device__ float g_inv0[NDIM];   // accumulates sum(z0^2), then holds 1/norm
__device__ float g_inv1[NDIM];
__device__ float g_S[NDIM];
__device__ float g_P[NDIM];

__device__ __forceinline__ uint32_t f2tf32(float f) {
    uint32_t u;
    asm("cvt.rna.tf32.f32 %0, %1;" : "=r"(u) : "f"(f));
    return u;
}

__device__ __forceinline__ void mma_tf32(float c[4],
                                         const uint32_t a[4],
                                         const uint32_t b[2]) {
    asm volatile(
        "mma.sync.aligned.m16n8k8.row.col.f32.tf32.tf32.f32 "
        "{%0,%1,%2,%3}, {%4,%5,%6,%7}, {%8,%9}, {%0,%1,%2,%3};"
        : "+f"(c[0]), "+f"(c[1]), "+f"(c[2]), "+f"(c[3])
        : "r"(a[0]), "r"(a[1]), "r"(a[2]), "r"(a[3]),
          "r"(b[0]), "r"(b[1]));
}

__device__ __forceinline__ void mma_bf16(float c[4],
                                         const uint32_t a[4],
                                         const uint32_t b[2]) {
    asm volatile(
        "mma.sync.aligned.m16n8k16.row.col.f32.bf16.bf16.f32 "
        "{%0,%1,%2,%3}, {%4,%5,%6,%7}, {%8,%9}, {%0,%1,%2,%3};"
        : "+f"(c[0]), "+f"(c[1]), "+f"(c[2]), "+f"(c[3])
        : "r"(a[0]), "r"(a[1]), "r"(a[2]), "r"(a[3]),
          "r"(b[0]), "r"(b[1]));
}

// ---------------------------------------------------------------------------
// MLP fragment-ordered smem fill (R5/R10 structure)
// ---------------------------------------------------------------------------
__device__ __forceinline__ void fill_tiles(
    uint32_t* sA, uint32_t* sB,
    const float* __restrict__ A, const float* __restrict__ B,
    int rowBase, int colBase, int K, int k0, int t)
{
#pragma unroll
    for (int v = 0; v < 4; v++) {
        int idx = t + v * 256;
        int row = idx >> 3;
        int q   = idx & 7;
        int ks  = q >> 1;
        int e2  = q & 1;

        float4 va = *reinterpret_cast<const float4*>(
            &A[(size_t)(rowBase + row) * K + k0 + (q << 2)]);
        {
            int mt = row >> 4;
            int rr = row & 15;
            int r  = (rr >> 3) + (e2 << 1);
            uint32_t* p = &sA[(((((mt << 2) + ks) << 5) + ((rr & 7) << 2)) << 2) + r];
            p[0]  = f2tf32(va.x);
            p[4]  = f2tf32(va.y);
            p[8]  = f2tf32(va.z);
            p[12] = f2tf32(va.w);
        }
        float4 vb = *reinterpret_cast<const float4*>(
            &B[(size_t)(colBase + row) * K + k0 + (q << 2)]);
        {
            int nt = row >> 3;
            uint32_t* p = &sB[((((((nt << 2) + ks) << 5) + ((row & 7) << 2))) << 1) + e2];
            p[0] = f2tf32(vb.x);
            p[2] = f2tf32(vb.y);
            p[4] = f2tf32(vb.z);
            p[6] = f2tf32(vb.w);
        }
    }
}

// ---------------------------------------------------------------------------
// MLP GEMM: C = act(A @ B^T + bias). R5/R10 structure: static smem,
// single-buffered, 2 CTAs/SM (cross-CTA overlap hides fill latency).
// doElu==1 (layer 1): also zeroes g_inv/g_S/g_P.
// doElu==0 (layer 2): epilogue emits bf16 z copy + per-row sum(z^2).
// ---------------------------------------------------------------------------
__global__ __launch_bounds__(NTHREADS, 2) void gemm_bias_act_mma(
    const float* __restrict__ A0, const float* __restrict__ A1,
    const float* __restrict__ B, const float* __restrict__ bias,
    float* __restrict__ C0, float* __restrict__ C1,
    int K, int Nn, int doElu)
{
    __shared__ uint32_t sA[4096];
    __shared__ uint32_t sB[4096];
    __shared__ float sRow[BM];

    const float* A = (blockIdx.z == 0) ? A0 : A1;
    float* C = (blockIdx.z == 0) ? C0 : C1;
    __nv_bfloat16* Cb = (blockIdx.z == 0) ? g_z0b : g_z1b;
    float* gSS = (blockIdx.z == 0) ? g_inv0 : g_inv1;

    const int t = threadIdx.x;
    const int wid = t >> 5, lane = t & 31;
    const int wm = wid >> 2, wn = wid & 3;
    const int rowBase = blockIdx.y * BM;
    const int colBase = blockIdx.x * BN;

    // Layer-1 auxiliary: zero the accumulators (layer 2 runs after, in-order).
    if (doElu && blockIdx.x == 0 && blockIdx.z == 0) {
        int idx = blockIdx.y * NTHREADS + t;   // 64*256 = 16384 >= 8192
        if (idx < NDIM) {
            g_inv0[idx] = 0.0f; g_inv1[idx] = 0.0f;
            g_S[idx] = 0.0f;    g_P[idx] = 0.0f;
        }
    }
    if (!doElu && t < BM) sRow[t] = 0.0f;

    float acc[4][4][4];
#pragma unroll
    for (int i = 0; i < 4; i++)
#pragma unroll
        for (int j = 0; j < 4; j++)
#pragma unroll
            for (int r = 0; r < 4; r++) acc[i][j][r] = 0.0f;

    for (int k0 = 0; k0 < K; k0 += BK) {
        fill_tiles(sA, sB, A, B, rowBase, colBase, K, k0, t);
        __syncthreads();

#pragma unroll
        for (int ks = 0; ks < 4; ks++) {
            uint32_t af[4][4];
            uint32_t bf[4][2];
#pragma unroll
            for (int am = 0; am < 4; am++) {
                uint4 v = *reinterpret_cast<const uint4*>(
                    &sA[(((((wm << 2) + am) << 2) + ks) << 5 | lane) << 2]);
                af[am][0] = v.x; af[am][1] = v.y; af[am][2] = v.z; af[am][3] = v.w;
            }
#pragma unroll
            for (int bn = 0; bn < 4; bn++) {
                uint2 v = *reinterpret_cast<const uint2*>(
                    &sB[(((((wn << 2) + bn) << 2) + ks) << 5 | lane) << 1]);
                bf[bn][0] = v.x; bf[bn][1] = v.y;
            }
#pragma unroll
            for (int am = 0; am < 4; am++)
#pragma unroll
                for (int bn = 0; bn < 4; bn++)
                    mma_tf32(acc[am][bn], af[am], bf[bn]);
        }
        __syncthreads();
    }

    // Epilogue
#pragma unroll
    for (int am = 0; am < 4; am++) {
        int rloc0 = wm * 64 + am * 16 + (lane >> 2);
        int row0 = rowBase + rloc0;
        float ss0 = 0.0f, ss1 = 0.0f;
#pragma unroll
        for (int bn = 0; bn < 4; bn++) {
            int col = colBase + wn * 32 + bn * 8 + ((lane & 3) << 1);
            float b0 = bias[col], b1 = bias[col + 1];
            float v0 = acc[am][bn][0] + b0;
            float v1 = acc[am][bn][1] + b1;
            float v2 = acc[am][bn][2] + b0;
            float v3 = acc[am][bn][3] + b1;
            if (doElu) {
                v0 = (v0 > 0.0f) ? v0 : expm1f(v0);
                v1 = (v1 > 0.0f) ? v1 : expm1f(v1);
                v2 = (v2 > 0.0f) ? v2 : expm1f(v2);
                v3 = (v3 > 0.0f) ? v3 : expm1f(v3);
            }
            float2 lo = {v0, v1}, hi = {v2, v3};
            *reinterpret_cast<float2*>(&C[(size_t)row0 * Nn + col]) = lo;
            *reinterpret_cast<float2*>(&C[(size_t)(row0 + 8) * Nn + col]) = hi;
            if (!doElu) {
                __nv_bfloat162 p0 = __floats2bfloat162_rn(v0, v1);
                __nv_bfloat162 p1 = __floats2bfloat162_rn(v2, v3);
                *reinterpret_cast<uint32_t*>(&Cb[(size_t)row0 * Nn + col]) =
                    *reinterpret_cast<uint32_t*>(&p0);
                *reinterpret_cast<uint32_t*>(&Cb[(size_t)(row0 + 8) * Nn + col]) =
                    *reinterpret_cast<uint32_t*>(&p1);
                ss0 += v0 * v0 + v1 * v1;
                ss1 += v2 * v2 + v3 * v3;
            }
        }
        if (!doElu) {
#pragma unroll
            for (int off = 1; off < 4; off <<= 1) {
                ss0 += __shfl_xor_sync(0xffffffffu, ss0, off);
                ss1 += __shfl_xor_sync(0xffffffffu, ss1, off);
            }
            if ((lane & 3) == 0) {
                atomicAdd(&sRow[rloc0], ss0);
                atomicAdd(&sRow[rloc0 + 8], ss1);
            }
        }
    }
    if (!doElu) {
        __syncthreads();
        if (t < BM) atomicAdd(&gSS[rowBase + t], sRow[t]);
    }
}

// ---------------------------------------------------------------------------
// norm_finish: convert accumulated sum(z^2) -> 1/norm.
// ---------------------------------------------------------------------------
__global__ void norm_finish_kernel()
{
    int idx = blockIdx.x * 256 + threadIdx.x;
    if (idx < NDIM) {
        g_inv0[idx] = rsqrtf(g_inv0[idx]);
        g_inv1[idx] = rsqrtf(g_inv1[idx]);
    }
}

// ---------------------------------------------------------------------------
// Fused similarity (bf16 m16n8k16): block 128x256, warp 64x64, BK=32,
// double-buffered; per iter: LDG(it+1) early -> mma(it) -> STS(it+1) -> sync.
// (R11 structure — measured at the legacy-mma ceiling.)
// ---------------------------------------------------------------------------
__global__ __launch_bounds__(NTHREADS, 1) void sim_fused_bf16(
    const float* __restrict__ pos)
{
    extern __shared__ uint32_t dynsmem[];
    uint32_t* sA = dynsmem;                          // [2][SA_WORDS]
    uint32_t* sB = dynsmem + 2 * SA_WORDS;           // [2][SB_WORDS]
    float* sS = (float*)(dynsmem + 2 * SA_WORDS + 2 * SB_WORDS);
    float* sP = sS + SBM;

    const int t = threadIdx.x;
    const int wid = t >> 5, lane = t & 31;
    const int wm = wid >> 2, wn = wid & 3;
    const int rowBase = blockIdx.y * SBM;
    const int colBase = blockIdx.x * SBN;

    if (t < SBM) { sS[t] = 0.0f; sP[t] = 0.0f; }

    uint32_t offA[2]; const __nv_bfloat16* gA[2];
    uint32_t offB[4]; const __nv_bfloat16* gB[4];
#pragma unroll
    for (int v = 0; v < 2; v++) {
        int idx = t + v * 256;
        int row = idx >> 2;
        int c   = idx & 3;
        int ks  = c >> 1;
        int hi  = c & 1;
        int mt  = row >> 4;
        int rr  = row & 15;
        offA[v] = (uint32_t)((((mt * 2 + ks) * 32 + (rr & 7) * 4) << 2)
                             + (rr >> 3) + (hi << 1));
        gA[v] = g_z0b + (size_t)(rowBase + row) * HDIM + c * 8;
    }
#pragma unroll
    for (int v = 0; v < 4; v++) {
        int idx = t + v * 256;
        int n   = idx >> 2;
        int c   = idx & 3;
        int ks  = c >> 1;
        int hi  = c & 1;
        int nt  = n >> 3;
        offB[v] = (uint32_t)((((nt * 2 + ks) * 32 + (n & 7) * 4) << 1) + hi);
        gB[v] = g_z1b + (size_t)(colBase + n) * HDIM + c * 8;
    }

    float acc[4][8][4];
#pragma unroll
    for (int i = 0; i < 4; i++)
#pragma unroll
        for (int j = 0; j < 8; j++)
#pragma unroll
            for (int r = 0; r < 4; r++) acc[i][j][r] = 0.0f;

    {
#pragma unroll
        for (int v = 0; v < 2; v++) {
            uint4 w = *reinterpret_cast<const uint4*>(gA[v]);
            uint32_t* p = &sA[offA[v]];
            p[0] = w.x; p[4] = w.y; p[8] = w.z; p[12] = w.w;
        }
#pragma unroll
        for (int v = 0; v < 4; v++) {
            uint4 w = *reinterpret_cast<const uint4*>(gB[v]);
            uint32_t* p = &sB[offB[v]];
            p[0] = w.x; p[2] = w.y; p[4] = w.z; p[6] = w.w;
        }
    }
    __syncthreads();

    const int NITER = HDIM / SBK;   // 16
    for (int it = 0; it < NITER; it++) {
        const int cur = it & 1;
        const uint32_t* cA = sA + cur * SA_WORDS;
        const uint32_t* cB = sB + cur * SB_WORDS;
        const bool pf = (it + 1 < NITER);

        uint4 wA[2], wB[4];
        if (pf) {
            const int kn = (it + 1) * SBK;
#pragma unroll
            for (int v = 0; v < 2; v++)
                wA[v] = *reinterpret_cast<const uint4*>(gA[v] + kn);
#pragma unroll
            for (int v = 0; v < 4; v++)
                wB[v] = *reinterpret_cast<const uint4*>(gB[v] + kn);
        }

#pragma unroll
        for (int ks = 0; ks < 2; ks++) {
            uint32_t af[4][4];
            uint32_t bf[8][2];
#pragma unroll
            for (int am = 0; am < 4; am++) {
                uint4 v = *reinterpret_cast<const uint4*>(
                    &cA[((((wm * 4 + am) * 2 + ks) * 32 + lane) << 2)]);
                af[am][0] = v.x; af[am][1] = v.y; af[am][2] = v.z; af[am][3] = v.w;
            }
#pragma unroll
            for (int bn = 0; bn < 8; bn++) {
                uint2 v = *reinterpret_cast<const uint2*>(
                    &cB[((((wn * 8 + bn) * 2 + ks) * 32 + lane) << 1)]);
                bf[bn][0] = v.x; bf[bn][1] = v.y;
            }
#pragma unroll
            for (int am = 0; am < 4; am++)
#pragma unroll
                for (int bn = 0; bn < 8; bn++)
                    mma_bf16(acc[am][bn], af[am], bf[bn]);
        }

        if (pf) {
            uint32_t* dA = sA + (cur ^ 1) * SA_WORDS;
            uint32_t* dB = sB + (cur ^ 1) * SB_WORDS;
#pragma unroll
            for (int v = 0; v < 2; v++) {
                uint32_t* p = &dA[offA[v]];
                p[0] = wA[v].x; p[4] = wA[v].y; p[8] = wA[v].z; p[12] = wA[v].w;
            }
#pragma unroll
            for (int v = 0; v < 4; v++) {
                uint32_t* p = &dB[offB[v]];
                p[0] = wB[v].x; p[2] = wB[v].y; p[4] = wB[v].z; p[6] = wB[v].w;
            }
        }
        __syncthreads();
    }

    // Epilogue: exp(cos/tau), weight by pos, per-row reduce
#pragma unroll
    for (int am = 0; am < 4; am++) {
        int rloc0 = wm * 64 + am * 16 + (lane >> 2);
        int row0 = rowBase + rloc0;
        float ii0 = g_inv0[row0] * TAU_INV;
        float ii1 = g_inv0[row0 + 8] * TAU_INV;
        float s0 = 0.0f, p0 = 0.0f, s1 = 0.0f, p1 = 0.0f;
#pragma unroll
        for (int bn = 0; bn < 8; bn++) {
            int col = colBase + wn * 64 + bn * 8 + ((lane & 3) << 1);
            float j0 = g_inv1[col];
            float j1 = g_inv1[col + 1];
            float2 pv0 = *reinterpret_cast<const float2*>(
                &pos[(size_t)row0 * NDIM + col]);
            float2 pv1 = *reinterpret_cast<const float2*>(
                &pos[(size_t)(row0 + 8) * NDIM + col]);
            float m;
            m = expf(acc[am][bn][0] * ii0 * j0); s0 += m; p0 += m * pv0.x;
            m = expf(acc[am][bn][1] * ii0 * j1); s0 += m; p0 += m * pv0.y;
            m = expf(acc[am][bn][2] * ii1 * j0); s1 += m; p1 += m * pv1.x;
            m = expf(acc[am][bn][3] * ii1 * j1); s1 += m; p1 += m * pv1.y;
        }
#pragma unroll
        for (int off = 1; off < 4; off <<= 1) {
            s0 += __shfl_xor_sync(0xffffffffu, s0, off);
            p0 += __shfl_xor_sync(0xffffffffu, p0, off);
            s1 += __shfl_xor_sync(0xffffffffu, s1, off);
            p1 += __shfl_xor_sync(0xffffffffu, p1, off);
        }
        if ((lane & 3) == 0) {
            atomicAdd(&sS[rloc0], s0);
            atomicAdd(&sP[rloc0], p0);
            atomicAdd(&sS[rloc0 + 8], s1);
            atomicAdd(&sP[rloc0 + 8], p1);
        }
    }
    __syncthreads();
    if (t < SBM) {
        atomicAdd(&g_S[rowBase + t], sS[t]);
        atomicAdd(&g_P[rowBase + t], sP[t]);
    }
}

// ---------------------------------------------------------------------------
// Final loss: -mean(log(P/(S+eps)+eps))
// ---------------------------------------------------------------------------
__global__ void loss_kernel(float* __restrict__ loss_out)
{
    float local = 0.0f;
    for (int i = threadIdx.x; i < NDIM; i += 256) {
        local += logf(g_P[i] / (g_S[i] + EPSV) + EPSV);
    }
#pragma unroll
    for (int off = 16; off; off >>= 1)
        local += __shfl_xor_sync(0xffffffffu, local, off);

    __shared__ float sred[8];
    if ((threadIdx.x & 31) == 0) sred[threadIdx.x >> 5] = local;
    __syncthreads();
    if (threadIdx.x == 0) {
        float tot = 0.0f;
#pragma unroll
        for (int w = 0; w < 8; w++) tot += sred[w];
        loss_out[0] = -tot / (float)NDIM;
    }
}

// ---------------------------------------------------------------------------
// kernel_launch — inputs: embd0, embd1, pos, W1, b1, W2, b2
// output layout: [z0 (N*H) | z1 (N*H) | loss (1)]
// ---------------------------------------------------------------------------
extern "C" void kernel_launch(void* const* d_in, const int* in_sizes, int n_in,
                              void* d_out, int out_size)
{
    const float* embd0 = (const float*)d_in[0];
    const float* embd1 = (const float*)d_in[1];
    const float* pos   = (const float*)d_in[2];
    const float* W1    = (const float*)d_in[3];
    const float* b1    = (const float*)d_in[4];
    const float* W2    = (const float*)d_in[5];
    const float* b2    = (const float*)d_in[6];

    float* out = (float*)d_out;
    float* z0 = out;
    float* z1 = out + (size_t)NDIM * HDIM;
    float* loss = out + 2ull * NDIM * HDIM;

    float* h = nullptr;
    cudaGetSymbolAddress((void**)&h, g_h);
    float* h0 = h;
    float* h1 = h + (size_t)NDIM * HDIM;

    static bool attrDone = false;
    if (!attrDone) {
        cudaFuncSetAttribute(sim_fused_bf16,
                             cudaFuncAttributeMaxDynamicSharedMemorySize,
                             SIM_DSMEM);
        attrDone = true;
    }

    dim3 blk(NTHREADS);
    dim3 grid_mlp(HDIM / BN, NDIM / BM, 2);     // 4 x 64 x 2
    dim3 grid_sim(NDIM / SBN, NDIM / SBM);      // 32 x 64

    // Layer 1 (ELU) — also zeroes g_inv*/g_S/g_P
    gemm_bias_act_mma<<<grid_mlp, blk>>>(embd0, embd1, W1, b1, h0, h1,
                                         HDIM, HDIM, 1);
    // Layer 2 (linear) — also emits bf16 copies + per-row sum(z^2)
    gemm_bias_act_mma<<<grid_mlp, blk>>>(h0, h1, W2, b2, z0, z1,
                                         HDIM, HDIM, 0);
    // sum(z^2) -> 1/norm
    norm_finish_kernel<<<NDIM / 256, 256>>>();
    // Fused similarity + row reductions
    sim_fused_bf16<<<grid_sim, blk, SIM_DSMEM>>>(pos);
    // Scalar loss
    loss_kernel<<<1, 256>>>(loss);
}